// round 16
// baseline (speedup 1.0000x reference)
#include <cuda_runtime.h>
#include <cstdint>

// VectorQuantizer: int8 dp4a prune + exact fp32 rescore.
// out = [ z_q (2097152 f32) | loss (1 f32) | indices (32768 f32) ]

#define C_DIM    64
#define K_CB     1024
#define P_BLK    256
#define NT       256
#define Z_ELEMS  2097152
#define N_PIX    32768
#define GRID_MAIN (N_PIX / P_BLK)   // 128
#define CAP      12

// ---- device scratch ----
__device__ float    g_Et[C_DIM * K_CB];   // transposed codebook [c][k]
__device__ uint32_t g_eq[K_CB * 16];      // int8 codebook packed [k][16 words]
__device__ float    g_e2[K_CB];           // sum e^2 (sequential c)
__device__ uint32_t g_zq[N_PIX * 16];     // int8 z packed [n][16 words]
__device__ float    g_z2[N_PIX];          // sum z^2 (sequential c)
__device__ float    g_Wn[N_PIX];          // per-pixel safe window
__device__ double   g_sum;
__device__ unsigned g_ticket;

__device__ __forceinline__ int dp4a(uint32_t a, uint32_t b, int c) {
    int r;
    asm("dp4a.s32.s32 %0, %1, %2, %3;" : "=r"(r) : "r"(a), "r"(b), "r"(c));
    return r;
}
__device__ __forceinline__ void cp16(unsigned s, const void* g) {
    asm volatile("cp.async.ca.shared.global [%0], [%1], 16;\n" :: "r"(s), "l"(g));
}
__device__ __forceinline__ void cp_commit() { asm volatile("cp.async.commit_group;\n"); }
__device__ __forceinline__ void cp_wait0()  { asm volatile("cp.async.wait_group 0;\n"); }

#define QE_SCALE 130048.0f                 // |e| < 2^-10  =>  |qe| <= 127
#define NSC2     (-2.0f / 2080768.0f)      // -2 / (16 * 130048)

// ---------------------------------------------------------------------------
// Prep: Et transpose + int8 codebook pack + e2; per-pixel z2, qz pack, window.
// ---------------------------------------------------------------------------
__global__ void vq_prep(const float* __restrict__ cb, const float* __restrict__ z) {
    int id = blockIdx.x * blockDim.x + threadIdx.x;
    if (id == 0) { g_sum = 0.0; g_ticket = 0u; }

    if (id < 16384) {            // codebook: id = k*16 + (c4/4)
        int k  = id >> 4;
        int c4 = (id & 15) * 4;
        float4 v = *(const float4*)(cb + k * 64 + c4);
        g_Et[(c4 + 0) * 1024 + k] = v.x;
        g_Et[(c4 + 1) * 1024 + k] = v.y;
        g_Et[(c4 + 2) * 1024 + k] = v.z;
        g_Et[(c4 + 3) * 1024 + k] = v.w;
        int q0 = __float2int_rn(v.x * QE_SCALE);
        int q1 = __float2int_rn(v.y * QE_SCALE);
        int q2 = __float2int_rn(v.z * QE_SCALE);
        int q3 = __float2int_rn(v.w * QE_SCALE);
        g_eq[k * 16 + (c4 >> 2)] =
            (uint32_t)(q0 & 255) | ((uint32_t)(q1 & 255) << 8) |
            ((uint32_t)(q2 & 255) << 16) | ((uint32_t)(q3 & 255) << 24);
    }
    if (id < 1024) {             // e2: strict sequential over c
        const float* row = cb + id * 64;
        float s = 0.f;
        #pragma unroll
        for (int c = 0; c < 64; c++)
            s = __fadd_rn(s, __fmul_rn(row[c], row[c]));
        g_e2[id] = s;
    }
    if (id >= 16384 && id < 16384 + N_PIX) {
        int n = id - 16384;
        int b = n >> 10, p = n & 1023;
        const float* zp = z + (size_t)b * 65536 + p;
        float s = 0.f, sa = 0.f, rq2 = 0.f, ma = 0.f;
        uint32_t w = 0;
        #pragma unroll
        for (int c = 0; c < 64; c++) {
            float v = zp[c * 1024];
            s  = __fadd_rn(s, __fmul_rn(v, v));       // seq chain == lineage
            sa += fabsf(v);
            ma  = fmaxf(ma, fabsf(v));
            int q = __float2int_rn(v * 16.f);
            q = max(-127, min(127, q));
            float dz = v - (float)q * 0.0625f;
            rq2 += dz * dz;
            w |= (uint32_t)(q & 255) << ((c & 3) * 8);
            if ((c & 3) == 3) { g_zq[n * 16 + (c >> 2)] = w; w = 0; }
        }
        g_z2[n] = s;
        // W = 2*(qz*de + dz*e bounds) + fp margin ; Cauchy-Schwarz on dz.e
        float W = 2.f * (3.845e-6f * (sa + 4.01f) + sqrtf(rq2) * 7.8125e-3f)
                + 1e-4f;
        if (ma > 7.9f) W = 1e30f;   // clamp invalidated -> force coop fallback
        g_Wn[n] = W;
    }
}

// ---------------------------------------------------------------------------
// smem byte offsets
#define SO_ZT    0                          // 256*65*4 = 66560 exact fp32 z
#define SO_EQ    66560                      // 2*128*16*4 = 16384 int8 code tiles
#define SO_E2    82944                      // 2*128*4 = 1024
#define SO_CAND  83968                      // 256*CAP*4 = 12288
#define SO_WIN   96256                      // 1024
#define SO_RED   97280                      // 64 (8-aligned: 97280 % 8 == 0)
#define SM_TOTAL 97344

__global__ __launch_bounds__(NT, 2)
void vq_main(const float* __restrict__ z, const float* __restrict__ cb,
             float* __restrict__ out) {
    extern __shared__ char sm[];
    float*    sZt   = (float*)(sm + SO_ZT);      // [256 px][65]
    uint32_t* sEq   = (uint32_t*)(sm + SO_EQ);   // [2][128*16]
    float*    sE2   = (float*)(sm + SO_E2);      // [2][128]
    int*      sCand = (int*)(sm + SO_CAND);      // [256][CAP]
    int*      sWin  = (int*)(sm + SO_WIN);       // [256]
    double*   sRed  = (double*)(sm + SO_RED);    // [8]

    const int tid  = threadIdx.x;
    const int wid  = tid >> 5;
    const int lane = tid & 31;
    const int n0   = blockIdx.x * P_BLK;
    const int b    = n0 >> 10;
    const int p0   = n0 & 1023;
    const float* zb = z + (size_t)b * 65536 + p0;

    const unsigned uEq = (unsigned)__cvta_generic_to_shared(sEq);
    const unsigned uE2 = (unsigned)__cvta_generic_to_shared(sE2);

    // prefetch code tile 0 (int8 rows + e2)
    #pragma unroll
    for (int j = 0; j < 2; j++)
        cp16(uEq + (unsigned)(tid + j * NT) * 16u,
             (const char*)g_eq + (tid + j * NT) * 16);
    if (tid < 32) cp16(uE2 + (unsigned)tid * 16u, (const char*)g_e2 + tid * 16);
    cp_commit();

    // stage exact z -> sZt [px][65] (stride 65 => conflict-free)
    for (int i = tid; i < 64 * 256; i += NT) {
        int c = i >> 8, px = i & 255;
        sZt[px * 65 + c] = zb[c * 1024 + px];
    }

    // per-thread pixel state
    uint32_t zq[16];
    {
        const uint4* src = (const uint4*)(g_zq + (size_t)(n0 + tid) * 16);
        #pragma unroll
        for (int j = 0; j < 4; j++) {
            uint4 v = src[j];
            zq[4*j] = v.x; zq[4*j+1] = v.y; zq[4*j+2] = v.z; zq[4*j+3] = v.w;
        }
    }
    const float sz = g_z2[n0 + tid];
    const float W  = g_Wn[n0 + tid];
    float m1 = 1e30f;
    int   cnt = 0;

    // ---- scan: tile0 min-only, tiles 1..7 collect, tile0 revisit collect ----
    for (int it = 0; it < 9; ++it) {
        const int tile = (it == 8) ? 0 : it;
        cp_wait0();
        __syncthreads();
        if (it < 8) {
            const int nxt = (it == 7) ? 0 : it + 1;
            unsigned db = (unsigned)(((it + 1) & 1) * 8192);
            const char* se = (const char*)(g_eq + nxt * 2048);
            #pragma unroll
            for (int j = 0; j < 2; j++)
                cp16(uEq + db + (unsigned)(tid + j * NT) * 16u,
                     se + (tid + j * NT) * 16);
            if (tid < 32)
                cp16(uE2 + (unsigned)(((it + 1) & 1) * 512) + (unsigned)tid * 16u,
                     (const char*)(g_e2 + nxt * 128) + tid * 16);
            cp_commit();
        }
        const uint32_t* eb  = sEq + (it & 1) * 2048;
        const float*    e2b = sE2 + (it & 1) * 128;
        const bool collect  = (it > 0);
        const int  kb       = tile * 128;

        for (int i = 0; i < 128; i += 2) {
            const uint32_t* eA = eb + i * 16;
            uint4 a0 = *(const uint4*)(eA);
            uint4 a1 = *(const uint4*)(eA + 4);
            uint4 a2 = *(const uint4*)(eA + 8);
            uint4 a3 = *(const uint4*)(eA + 12);
            uint4 b0 = *(const uint4*)(eA + 16);
            uint4 b1 = *(const uint4*)(eA + 20);
            uint4 b2 = *(const uint4*)(eA + 24);
            uint4 b3 = *(const uint4*)(eA + 28);

            int pa0 = 0, pa1 = 0, pb0 = 0, pb1 = 0;
            pa0 = dp4a(zq[0],  a0.x, pa0);  pa1 = dp4a(zq[1],  a0.y, pa1);
            pb0 = dp4a(zq[0],  b0.x, pb0);  pb1 = dp4a(zq[1],  b0.y, pb1);
            pa0 = dp4a(zq[2],  a0.z, pa0);  pa1 = dp4a(zq[3],  a0.w, pa1);
            pb0 = dp4a(zq[2],  b0.z, pb0);  pb1 = dp4a(zq[3],  b0.w, pb1);
            pa0 = dp4a(zq[4],  a1.x, pa0);  pa1 = dp4a(zq[5],  a1.y, pa1);
            pb0 = dp4a(zq[4],  b1.x, pb0);  pb1 = dp4a(zq[5],  b1.y, pb1);
            pa0 = dp4a(zq[6],  a1.z, pa0);  pa1 = dp4a(zq[7],  a1.w, pa1);
            pb0 = dp4a(zq[6],  b1.z, pb0);  pb1 = dp4a(zq[7],  b1.w, pb1);
            pa0 = dp4a(zq[8],  a2.x, pa0);  pa1 = dp4a(zq[9],  a2.y, pa1);
            pb0 = dp4a(zq[8],  b2.x, pb0);  pb1 = dp4a(zq[9],  b2.y, pb1);
            pa0 = dp4a(zq[10], a2.z, pa0);  pa1 = dp4a(zq[11], a2.w, pa1);
            pb0 = dp4a(zq[10], b2.z, pb0);  pb1 = dp4a(zq[11], b2.w, pb1);
            pa0 = dp4a(zq[12], a3.x, pa0);  pa1 = dp4a(zq[13], a3.y, pa1);
            pb0 = dp4a(zq[12], b3.x, pb0);  pb1 = dp4a(zq[13], b3.y, pb1);
            pa0 = dp4a(zq[14], a3.z, pa0);  pa1 = dp4a(zq[15], a3.w, pa1);
            pb0 = dp4a(zq[14], b3.z, pb0);  pb1 = dp4a(zq[15], b3.w, pb1);

            float2 e2p = *(const float2*)(e2b + i);
            float dA = fmaf((float)(pa0 + pa1), NSC2, sz + e2p.x);
            float dB = fmaf((float)(pb0 + pb1), NSC2, sz + e2p.y);

            if (collect) {
                float thr = m1 + W;        // new minima always satisfy d < thr
                if (dA <= thr) { if (cnt < CAP) sCand[tid * CAP + cnt] = kb + i;     cnt++; }
                if (dB <= thr) { if (cnt < CAP) sCand[tid * CAP + cnt] = kb + i + 1; cnt++; }
            }
            m1 = fminf(m1, fminf(dA, dB));
        }
    }
    __syncthreads();

    // ---- exact rescore (identical rel_err=0 fp32 tree, explicit k tiebreak) ----
    float bd = 1e30f; int bk = 0;
    const bool ovf = (cnt > CAP);
    if (!ovf) {
        for (int i = 0; i < cnt; i++) {
            int k = sCand[tid * CAP + i];
            const float* er = cb + k * 64;
            float s = 0.f;
            #pragma unroll
            for (int c = 0; c < 64; c++)
                s = __fmaf_rn(sZt[tid * 65 + c], er[c], s);
            float dd = __fmaf_rn(s, -2.f, __fadd_rn(sz, g_e2[k]));
            if (dd < bd || (dd == bd && k < bk)) { bd = dd; bk = k; }
        }
    }
    // warp-cooperative full scan for overflow pixels (rare)
    unsigned obal = __ballot_sync(0xffffffffu, ovf);
    while (obal) {
        int src = __ffs(obal) - 1;
        obal &= obal - 1;
        int px = (wid << 5) + src;
        float szp = g_z2[n0 + px];
        float lbd = 1e30f; int lbk = 1 << 30;
        for (int k = lane; k < 1024; k += 32) {
            const float* er = cb + k * 64;
            float s = 0.f;
            #pragma unroll
            for (int c = 0; c < 64; c++)
                s = __fmaf_rn(sZt[px * 65 + c], er[c], s);
            float dd = __fmaf_rn(s, -2.f, __fadd_rn(szp, g_e2[k]));
            if (dd < lbd || (dd == lbd && k < lbk)) { lbd = dd; lbk = k; }
        }
        #pragma unroll
        for (int off = 16; off >= 1; off >>= 1) {
            float od = __shfl_xor_sync(0xffffffffu, lbd, off);
            int   ok = __shfl_xor_sync(0xffffffffu, lbk, off);
            if (od < lbd || (od == lbd && ok < lbk)) { lbd = od; lbk = ok; }
        }
        if (lane == src) { bd = lbd; bk = lbk; }
    }
    sWin[tid] = bk;
    out[(size_t)Z_ELEMS + 1 + n0 + tid] = (float)bk;
    __syncthreads();

    // ---- epilogue: z_q + loss (verified in R13) ----
    double lsum = 0.0;
    for (int i = tid; i < P_BLK * C_DIM; i += NT) {
        int c = i >> 8, px = i & 255;
        int k = sWin[px];
        float ev  = g_Et[c * 1024 + k];
        float zv  = sZt[px * 65 + c];
        float tdf = __fadd_rn(ev, -zv);
        out[(size_t)b * 65536 + c * 1024 + p0 + px] = __fadd_rn(zv, tdf);
        lsum += (double)__fmul_rn(tdf, tdf);
    }
    #pragma unroll
    for (int off = 16; off >= 1; off >>= 1)
        lsum += __shfl_down_sync(0xffffffffu, lsum, off);
    if (lane == 0) sRed[wid] = lsum;
    __syncthreads();

    if (tid == 0) {
        double s = 0.0;
        #pragma unroll
        for (int w = 0; w < 8; w++) s += sRed[w];
        atomicAdd(&g_sum, s);
        __threadfence();
        unsigned tk = atomicAdd(&g_ticket, 1u);
        if (tk == (unsigned)(gridDim.x - 1)) {
            double tot = atomicAdd(&g_sum, 0.0);
            float mf = (float)(tot / (double)Z_ELEMS);
            out[Z_ELEMS] = __fadd_rn(mf, __fmul_rn(0.25f, mf));
        }
    }
}

extern "C" void kernel_launch(void* const* d_in, const int* in_sizes, int n_in,
                              void* d_out, int out_size) {
    const float* z  = (const float*)d_in[0];
    const float* cb = (const float*)d_in[1];
    float* out = (float*)d_out;

    cudaFuncSetAttribute(vq_main, cudaFuncAttributeMaxDynamicSharedMemorySize,
                         SM_TOTAL);
    vq_prep<<<192, 256>>>(cb, z);
    vq_main<<<GRID_MAIN, NT, SM_TOTAL>>>(z, cb, out);
}

// round 17
// speedup vs baseline: 2.9992x; 2.9992x over previous
#include <cuda_runtime.h>
#include <cuda_fp16.h>
#include <cstdint>

// VectorQuantizer: native-HFMA2 half2 prune + exact fp32 rescore.
// out = [ z_q (2097152 f32) | loss (1 f32) | indices (32768 f32) ]

#define C_DIM    64
#define K_CB     1024
#define P_BLK    32
#define NT       256
#define Z_ELEMS  2097152
#define N_PIX    32768
#define GRID_MAIN (N_PIX / P_BLK)   // 1024
#define NTILES   8                  // 8 tiles x 128 codes
#define CAP      16

// ---- device scratch ----
__device__ float    g_Et[C_DIM * K_CB];   // transposed codebook [c][k]
__device__ __half   g_Eh[C_DIM * K_CB];   // half codebook*1024, [c][k]
__device__ float    g_e2[K_CB];           // sum e^2 (sequential c)
__device__ float    g_z2[N_PIX];          // sum z^2 (sequential c)
__device__ float    g_Wn[N_PIX];          // per-pixel provable window
__device__ double   g_sum;
__device__ unsigned g_ticket;

__device__ __forceinline__ void cp16(unsigned s, const void* g) {
    asm volatile("cp.async.ca.shared.global [%0], [%1], 16;\n" :: "r"(s), "l"(g));
}
__device__ __forceinline__ void cp_commit() { asm volatile("cp.async.commit_group;\n"); }
__device__ __forceinline__ void cp_wait0()  { asm volatile("cp.async.wait_group 0;\n"); }

#define NSC (-0.001953125f)   // -2/1024, exact

// ---------------------------------------------------------------------------
// Prep: Et transpose + half codebook (x1024); e2; per-pixel z2 + window.
// ---------------------------------------------------------------------------
__global__ void vq_prep(const float* __restrict__ cb, const float* __restrict__ z) {
    int id = blockIdx.x * blockDim.x + threadIdx.x;
    if (id == 0) { g_sum = 0.0; g_ticket = 0u; }

    if (id < 16384) {            // id = k*16 + c4/4
        int k  = id >> 4;
        int c4 = (id & 15) * 4;
        float4 v = *(const float4*)(cb + k * 64 + c4);
        g_Et[(c4 + 0) * 1024 + k] = v.x;
        g_Et[(c4 + 1) * 1024 + k] = v.y;
        g_Et[(c4 + 2) * 1024 + k] = v.z;
        g_Et[(c4 + 3) * 1024 + k] = v.w;
        g_Eh[(c4 + 0) * 1024 + k] = __float2half_rn(v.x * 1024.f);
        g_Eh[(c4 + 1) * 1024 + k] = __float2half_rn(v.y * 1024.f);
        g_Eh[(c4 + 2) * 1024 + k] = __float2half_rn(v.z * 1024.f);
        g_Eh[(c4 + 3) * 1024 + k] = __float2half_rn(v.w * 1024.f);
    }
    if (id < 1024) {             // e2: strict sequential over c
        const float* row = cb + id * 64;
        float s = 0.f;
        #pragma unroll
        for (int c = 0; c < 64; c++)
            s = __fadd_rn(s, __fmul_rn(row[c], row[c]));
        g_e2[id] = s;
    }
    if (id >= 16384 && id < 16384 + N_PIX) {
        int n = id - 16384;
        int b = n >> 10, p = n & 1023;
        const float* zp = z + (size_t)b * 65536 + p;
        float s = 0.f, S = 0.f, err = 0.f, cum = 0.f;
        #pragma unroll
        for (int c = 0; c < 64; c++) {
            float v = zp[c * 1024];
            s = __fadd_rn(s, __fmul_rn(v, v));    // seq chain == lineage
            float a = fabsf(v);
            S += a;
            cum += a;                             // |e_hat| <= 1 bound
            err += cum;                           // fma partial-sum roundings
            if ((c & 15) == 15) cum = 0.f;        // 4 chains of 16
        }
        g_z2[n] = s;
        float E = (err + 2.f * S) * (1.05f / 2048.f);   // scaled-domain bound
        g_Wn[n] = E * (4.f / 1024.f) + 1e-4f;           // W = 2*Delta + margin
    }
}

// ---------------------------------------------------------------------------
// smem byte offsets
#define SO_ZT    0                   // 32*65*4   = 8320  exact fp32 z [px][65]
#define SO_ZH    8320                // 64*32*4   = 8192  half2-dup z [c][px]
#define SO_EH    16512               // 2*64*128*2= 32768 half code tiles [c][k]
#define SO_E2    49280               // 2*128*4   = 1024
#define SO_CAND  50304               // 32*16*4   = 2048
#define SO_CNT   52352               // 128
#define SO_WIN   52480               // 128
#define SO_RED   52608               // 64  (52608 % 8 == 0)
#define SM_TOTAL 52672

__global__ __launch_bounds__(NT, 2)
void vq_main(const float* __restrict__ z, const float* __restrict__ cb,
             float* __restrict__ out) {
    extern __shared__ char sm[];
    float*   sZt   = (float*)(sm + SO_ZT);
    __half2* sZh   = (__half2*)(sm + SO_ZH);
    __half2* sEh   = (__half2*)(sm + SO_EH);
    float*   sE2   = (float*)(sm + SO_E2);
    int*     sCand = (int*)(sm + SO_CAND);
    int*     sCnt  = (int*)(sm + SO_CNT);
    int*     sWin  = (int*)(sm + SO_WIN);
    double*  sRed  = (double*)(sm + SO_RED);

    const int tid  = threadIdx.x;
    const int lane = tid & 31;
    const int wid  = tid >> 5;
    const int tx   = tid & 15;       // 8 codes: 8tx..8tx+7
    const int ty   = tid >> 4;       // px pair: 2ty, 2ty+1
    const int n0   = blockIdx.x * P_BLK;
    const int b    = n0 >> 10;
    const int p0   = n0 & 1023;
    const float* zb = z + (size_t)b * 65536 + p0;

    const unsigned uEH = (unsigned)__cvta_generic_to_shared(sm + SO_EH);
    const unsigned uE2 = (unsigned)__cvta_generic_to_shared(sm + SO_E2);

    // prefetch half code tile 0 (16KB: 1024 x 16B) + e2 tile 0
    #pragma unroll
    for (int j = 0; j < 4; j++) {
        int f = tid + j * NT;
        int c = f >> 4, jj = f & 15;
        cp16(uEH + (unsigned)(c * 256 + jj * 16),
             (const char*)g_Eh + c * 2048 + jj * 16);
    }
    if (tid < 32) cp16(uE2 + (unsigned)tid * 16u, (const char*)g_e2 + tid * 16);
    cp_commit();

    // stage exact z + half2-dup z
    for (int i = tid; i < 2048; i += NT) {
        int c = i >> 5, px = i & 31;
        float v = zb[c * 1024 + px];
        sZt[px * 65 + c] = v;
        sZh[c * 32 + px] = __half2half2(__float2half_rn(v));
    }
    if (tid < 32) sCnt[tid] = 0;

    const int pxa = 2 * ty, pxb_ = 2 * ty + 1;
    const float sz0 = g_z2[n0 + pxa], sz1 = g_z2[n0 + pxb_];
    const float W0  = g_Wn[n0 + pxa], W1  = g_Wn[n0 + pxb_];
    float m10 = 1e30f, m11 = 1e30f;

    // ---- scan: tiles 0..7 (tile0 min-only), then revisit tile 0 ----
    for (int it = 0; it < 9; ++it) {
        const int tile = (it == 8) ? 0 : it;
        cp_wait0();
        __syncthreads();
        if (it < 8) {
            const int nxt = (it == 7) ? 0 : it + 1;
            unsigned db = (unsigned)(((it + 1) & 1) * 16384);
            #pragma unroll
            for (int j = 0; j < 4; j++) {
                int f = tid + j * NT;
                int c = f >> 4, jj = f & 15;
                cp16(uEH + db + (unsigned)(c * 256 + jj * 16),
                     (const char*)g_Eh + c * 2048 + nxt * 256 + jj * 16);
            }
            if (tid < 32)
                cp16(uE2 + (unsigned)(((it + 1) & 1) * 512) + (unsigned)tid * 16u,
                     (const char*)(g_e2 + nxt * 128) + tid * 16);
            cp_commit();
        }

        const __half2* eb = sEh + (it & 1) * 4096;   // [c][64 half2]
        const float* e2b  = sE2 + (it & 1) * 128;
        const bool collect = (it > 0);
        const int  kb      = tile * 128;

        // e2 for my 8 codes
        float4 e2A = *(const float4*)(e2b + 8 * tx);
        float4 e2B = *(const float4*)(e2b + 8 * tx + 4);

        // 4 chains x 2 px x 4 code-pairs of half2 accumulators
        __half2 acc[4][2][4];
        #pragma unroll
        for (int q = 0; q < 4; q++)
            #pragma unroll
            for (int p = 0; p < 2; p++)
                #pragma unroll
                for (int j = 0; j < 4; j++)
                    acc[q][p][j] = __float2half2_rn(0.f);

        const __half2* erow = eb + 4 * tx;           // 4 half2 = 8 codes
        const __half2* zrow = sZh + pxa;             // 2 half2 dups

        // SW pipeline: stage holds channel c data, prefetch c+1 before FMAs
        uint4 eS = *(const uint4*)(erow);
        uint2 zS = *(const uint2*)(zrow);

        #pragma unroll
        for (int q = 0; q < 4; q++) {
            #pragma unroll
            for (int cc = 0; cc < 16; cc++) {
                const int c  = q * 16 + cc;
                const int nc = (c + 1) & 63;
                uint4 eC = eS; uint2 zC = zS;
                eS = *(const uint4*)(erow + nc * 64);
                zS = *(const uint2*)(zrow + nc * 32);

                __half2 e0 = *(__half2*)&eC.x, e1 = *(__half2*)&eC.y;
                __half2 e2h = *(__half2*)&eC.z, e3 = *(__half2*)&eC.w;
                __half2 z0 = *(__half2*)&zC.x, z1 = *(__half2*)&zC.y;
                acc[q][0][0] = __hfma2(z0, e0, acc[q][0][0]);
                acc[q][0][1] = __hfma2(z0, e1, acc[q][0][1]);
                acc[q][0][2] = __hfma2(z0, e2h, acc[q][0][2]);
                acc[q][0][3] = __hfma2(z0, e3, acc[q][0][3]);
                acc[q][1][0] = __hfma2(z1, e0, acc[q][1][0]);
                acc[q][1][1] = __hfma2(z1, e1, acc[q][1][1]);
                acc[q][1][2] = __hfma2(z1, e2h, acc[q][1][2]);
                acc[q][1][3] = __hfma2(z1, e3, acc[q][1][3]);
            }
        }

        // combine (half->float exact), compute d, collect, tile-min
        float thr0 = m10 + W0, thr1 = m11 + W1;
        float tmn0 = 1e30f, tmn1 = 1e30f;
        float e2v[8] = { e2A.x, e2A.y, e2A.z, e2A.w,
                         e2B.x, e2B.y, e2B.z, e2B.w };
        #pragma unroll
        for (int p = 0; p < 2; p++) {
            const float szp = p ? sz1 : sz0;
            const float thp = p ? thr1 : thr0;
            const int   pxl = pxa + p;
            float tm = 1e30f;
            #pragma unroll
            for (int j = 0; j < 4; j++) {
                float lo = __low2float(acc[0][p][j])  + __low2float(acc[1][p][j])
                         + __low2float(acc[2][p][j])  + __low2float(acc[3][p][j]);
                float hi = __high2float(acc[0][p][j]) + __high2float(acc[1][p][j])
                         + __high2float(acc[2][p][j]) + __high2float(acc[3][p][j]);
                int k0 = kb + 8 * tx + 2 * j;
                float d0 = __fmaf_rn(lo, NSC, __fadd_rn(szp, e2v[2 * j]));
                float d1 = __fmaf_rn(hi, NSC, __fadd_rn(szp, e2v[2 * j + 1]));
                if (collect) {
                    if (d0 <= thp) {
                        int pos = atomicAdd(&sCnt[pxl], 1);
                        if (pos < CAP) sCand[pxl * CAP + pos] = k0;
                    }
                    if (d1 <= thp) {
                        int pos = atomicAdd(&sCnt[pxl], 1);
                        if (pos < CAP) sCand[pxl * CAP + pos] = k0 + 1;
                    }
                }
                tm = fminf(tm, fminf(d0, d1));
            }
            if (p) tmn1 = tm; else tmn0 = tm;
        }
        // reduce tile-min across the 16 tx lanes sharing the px pair
        #pragma unroll
        for (int off = 8; off >= 1; off >>= 1) {
            tmn0 = fminf(tmn0, __shfl_xor_sync(0xffffffffu, tmn0, off));
            tmn1 = fminf(tmn1, __shfl_xor_sync(0xffffffffu, tmn1, off));
        }
        m10 = fminf(m10, tmn0);
        m11 = fminf(m11, tmn1);
    }
    __syncthreads();

    // ---- exact rescore (identical rel_err=0 fp32 tree; validated in R16) ----
    if (tid < 32) {
        const int px = tid;
        const float szp = g_z2[n0 + px];
        const int cv = sCnt[px];
        float bd = 1e30f; int bk = 0;
        bool ovf = (cv > CAP);
        if (!ovf) {
            for (int i = 0; i < cv; i++) {
                int k = sCand[px * CAP + i];
                const float* er = cb + k * 64;
                float s = 0.f;
                #pragma unroll
                for (int c = 0; c < 64; c++)
                    s = __fmaf_rn(sZt[px * 65 + c], er[c], s);
                float dd = __fmaf_rn(s, -2.f, __fadd_rn(szp, g_e2[k]));
                if (dd < bd || (dd == bd && k < bk)) { bd = dd; bk = k; }
            }
        }
        // warp-cooperative full scan for overflow pixels (rare)
        unsigned obal = __ballot_sync(0xffffffffu, ovf);
        while (obal) {
            int src = __ffs(obal) - 1;
            obal &= obal - 1;
            float szs = g_z2[n0 + src];
            float lbd = 1e30f; int lbk = 1 << 30;
            for (int k = lane; k < 1024; k += 32) {
                const float* er = cb + k * 64;
                float s = 0.f;
                #pragma unroll
                for (int c = 0; c < 64; c++)
                    s = __fmaf_rn(sZt[src * 65 + c], er[c], s);
                float dd = __fmaf_rn(s, -2.f, __fadd_rn(szs, g_e2[k]));
                if (dd < lbd || (dd == lbd && k < lbk)) { lbd = dd; lbk = k; }
            }
            #pragma unroll
            for (int off = 16; off >= 1; off >>= 1) {
                float od = __shfl_xor_sync(0xffffffffu, lbd, off);
                int   ok = __shfl_xor_sync(0xffffffffu, lbk, off);
                if (od < lbd || (od == lbd && ok < lbk)) { lbd = od; lbk = ok; }
            }
            if (lane == src) { bd = lbd; bk = lbk; }
        }
        sWin[px] = bk;
        out[(size_t)Z_ELEMS + 1 + n0 + px] = (float)bk;
    }
    __syncthreads();

    // ---- epilogue: z_q + loss (validated) ----
    double lsum = 0.0;
    for (int i = tid; i < 2048; i += NT) {
        int c = i >> 5, px = i & 31;
        int k = sWin[px];
        float ev  = g_Et[c * 1024 + k];
        float zv  = sZt[px * 65 + c];
        float tdf = __fadd_rn(ev, -zv);
        out[(size_t)b * 65536 + c * 1024 + p0 + px] = __fadd_rn(zv, tdf);
        lsum += (double)__fmul_rn(tdf, tdf);
    }
    #pragma unroll
    for (int off = 16; off >= 1; off >>= 1)
        lsum += __shfl_down_sync(0xffffffffu, lsum, off);
    if (lane == 0) sRed[wid] = lsum;
    __syncthreads();

    if (tid == 0) {
        double s = 0.0;
        #pragma unroll
        for (int w = 0; w < 8; w++) s += sRed[w];
        atomicAdd(&g_sum, s);
        __threadfence();
        unsigned tk = atomicAdd(&g_ticket, 1u);
        if (tk == (unsigned)(gridDim.x - 1)) {
            double tot = atomicAdd(&g_sum, 0.0);
            float mf = (float)(tot / (double)Z_ELEMS);
            out[Z_ELEMS] = __fadd_rn(mf, __fmul_rn(0.25f, mf));
        }
    }
}

extern "C" void kernel_launch(void* const* d_in, const int* in_sizes, int n_in,
                              void* d_out, int out_size) {
    const float* z  = (const float*)d_in[0];
    const float* cb = (const float*)d_in[1];
    float* out = (float*)d_out;

    cudaFuncSetAttribute(vq_main, cudaFuncAttributeMaxDynamicSharedMemorySize,
                         SM_TOTAL);
    vq_prep<<<192, 256>>>(cb, z);
    vq_main<<<GRID_MAIN, NT, SM_TOTAL>>>(z, cb, out);
}